// round 1
// baseline (speedup 1.0000x reference)
#include <cuda_runtime.h>
#include <cstdint>

// Problem constants
#define B_    32
#define C_    128
#define H_    56
#define W_    56
#define OC_   256
#define HW_   (H_ * W_)          // 3136
#define KDIM  1152               // C*3*3
#define M_    (B_ * HW_)         // 100352

// Tiling
#define BM    128
#define BN    128
#define BK    16
#define NSTEP (KDIM / BK)        // 72

// Transposed weights: Wt[k][oc], filled by a tiny prep kernel each call.
__device__ float g_Wt[KDIM * OC_];

__global__ void transpose_w_kernel(const float* __restrict__ Wm) {
    int idx = blockIdx.x * blockDim.x + threadIdx.x;  // over OC_*KDIM
    if (idx < OC_ * KDIM) {
        int oc = idx / KDIM;
        int k  = idx - oc * KDIM;
        g_Wt[k * OC_ + oc] = Wm[idx];
    }
}

__device__ __forceinline__ unsigned smem_u32(const void* p) {
    return (unsigned)__cvta_generic_to_shared(p);
}
__device__ __forceinline__ void cpa4_zfill(unsigned dst, const float* src, bool pred) {
    asm volatile("cp.async.ca.shared.global [%0], [%1], 4, %2;\n"
                 :: "r"(dst), "l"(src), "r"(pred ? 4 : 0));
}
__device__ __forceinline__ void cpa16(unsigned dst, const float* src) {
    asm volatile("cp.async.cg.shared.global [%0], [%1], 16;\n"
                 :: "r"(dst), "l"(src));
}

__global__ __launch_bounds__(256, 2)
void conv_igemm_kernel(const float* __restrict__ x,
                       const float* __restrict__ bias,
                       float* __restrict__ out) {
    __shared__ float As[2][BK][BM];   // [k][pixel]
    __shared__ float Bs[2][BK][BN];   // [k][oc]

    const int tid = threadIdx.x;
    const int tx  = tid & 15;         // pixel-group index (fast store dim)
    const int ty  = tid >> 4;         // oc-group index
    const int m0  = blockIdx.x * BM;
    const int n0  = blockIdx.y * BN;

    // ---- A-load geometry: each thread owns one pixel column, 8 k-rows ----
    const int pix   = tid & 127;
    const int krow0 = tid >> 7;       // 0 or 1
    {
    }
    int p    = m0 + pix;
    int bimg = p / HW_;
    int hw   = p - bimg * HW_;
    const int h = hw / W_;
    const int w = hw - h * W_;
    // base for (c=0, kh=1, kw=1) i.e. center tap
    const float* xbase = x + (size_t)bimg * C_ * HW_ + h * W_ + w;

    float acc[8][8];
#pragma unroll
    for (int i = 0; i < 8; i++)
#pragma unroll
        for (int j = 0; j < 8; j++) acc[i][j] = 0.0f;

    // ---- stage loader (cp.async, zero-fill for halo) ----
    auto load_stage = [&](int s, int buf) {
        const int k0 = s * BK;
        // A: im2col gather, 8 scalar cp.async per thread
#pragma unroll
        for (int i = 0; i < 8; i++) {
            int krow = krow0 + 2 * i;
            int kk   = k0 + krow;
            int c    = kk / 9;
            int r    = kk - c * 9;
            int kh   = r / 3;
            int kw   = r - kh * 3;
            int ih   = h + kh - 1;
            int iw   = w + kw - 1;
            bool pred = ((unsigned)ih < (unsigned)H_) && ((unsigned)iw < (unsigned)W_);
            const float* src = xbase + c * HW_ + (kh - 1) * W_ + (kw - 1);
            cpa4_zfill(smem_u32(&As[buf][krow][pix]), src, pred);
        }
        // B: contiguous rows of Wt, 2x float4 per thread
#pragma unroll
        for (int i = 0; i < 2; i++) {
            int e   = tid + 256 * i;
            int kk  = e >> 5;             // 32 float4 per 128-float row
            int oc4 = (e & 31) << 2;
            cpa16(smem_u32(&Bs[buf][kk][oc4]),
                  g_Wt + (size_t)(k0 + kk) * OC_ + n0 + oc4);
        }
        asm volatile("cp.async.commit_group;\n");
    };

    load_stage(0, 0);

    for (int s = 0; s < NSTEP; s++) {
        if (s + 1 < NSTEP) {
            load_stage(s + 1, (s + 1) & 1);
            asm volatile("cp.async.wait_group 1;\n");
        } else {
            asm volatile("cp.async.wait_group 0;\n");
        }
        __syncthreads();

        const int buf = s & 1;
#pragma unroll
        for (int kk = 0; kk < BK; kk++) {
            float4 a0 = *(const float4*)&As[buf][kk][tx * 8];
            float4 a1 = *(const float4*)&As[buf][kk][tx * 8 + 4];
            float4 b0 = *(const float4*)&Bs[buf][kk][ty * 8];
            float4 b1 = *(const float4*)&Bs[buf][kk][ty * 8 + 4];
            float av[8] = {a0.x, a0.y, a0.z, a0.w, a1.x, a1.y, a1.z, a1.w};
            float bv[8] = {b0.x, b0.y, b0.z, b0.w, b1.x, b1.y, b1.z, b1.w};
#pragma unroll
            for (int i = 0; i < 8; i++)
#pragma unroll
                for (int j = 0; j < 8; j++)
                    acc[i][j] += av[i] * bv[j];
        }
        __syncthreads();
    }

    // ---- epilogue: bias + store (float4 along pixel dim, never crosses image) ----
    float bvals[8];
#pragma unroll
    for (int j = 0; j < 8; j++) bvals[j] = bias[n0 + ty * 8 + j];

#pragma unroll
    for (int i4 = 0; i4 < 8; i4 += 4) {
        int pp   = m0 + tx * 8 + i4;          // multiple of 4
        int bi   = pp / HW_;
        int hwp  = pp - bi * HW_;             // multiple of 4, hwp+3 < 3136
        float* obase = out + (size_t)bi * OC_ * HW_ + hwp;
#pragma unroll
        for (int j = 0; j < 8; j++) {
            int ocj = n0 + ty * 8 + j;
            float4 v = make_float4(acc[i4 + 0][j] + bvals[j],
                                   acc[i4 + 1][j] + bvals[j],
                                   acc[i4 + 2][j] + bvals[j],
                                   acc[i4 + 3][j] + bvals[j]);
            *(float4*)(obase + (size_t)ocj * HW_) = v;
        }
    }
}

extern "C" void kernel_launch(void* const* d_in, const int* in_sizes, int n_in,
                              void* d_out, int out_size) {
    const float* x  = (const float*)d_in[0];   // [B, C, H, W]
    const float* Wm = (const float*)d_in[1];   // [OC, C*3*3]
    const float* bb = (const float*)d_in[2];   // [OC]
    float* out      = (float*)d_out;           // [B, OC, H, W]

    transpose_w_kernel<<<(OC_ * KDIM + 255) / 256, 256>>>(Wm);

    dim3 grid(M_ / BM, OC_ / BN);   // 784 x 2
    conv_igemm_kernel<<<grid, 256>>>(x, bb, out);
}

// round 4
// speedup vs baseline: 1.4375x; 1.4375x over previous
#include <cuda_runtime.h>
#include <cuda_bf16.h>
#include <cstdint>

#define B_    32
#define C_    128
#define H_    56
#define W_    56
#define OC_   256
#define HW_   (H_ * W_)          // 3136
#define KDIM  1152               // C*9
#define M_    (B_ * HW_)         // 100352
#define NX_   (B_ * C_ * HW_)    // 12845056

#define BM    256
#define BN    128
#define BKW   32                 // original-k words per stage (64 interleaved bf16)
#define NSTAGE 36                // 1152/32
#define NT    512

// ---- static device scratch ----
__device__ __align__(16) unsigned g_xc[NX_];          // packed (hi | lo<<16) per x elem
__device__ __align__(16) unsigned g_wb1[OC_ * KDIM];  // (b_hi | b_hi<<16)
__device__ __align__(16) unsigned g_wb2[OC_ * KDIM];  // (b_lo | 0<<16)

__global__ void xprep_kernel(const float* __restrict__ x) {
    int i = blockIdx.x * blockDim.x + threadIdx.x;
    if (i < NX_) {
        float f = x[i];
        __nv_bfloat16 hb = __float2bfloat16(f);
        float fh = __bfloat162float(hb);
        __nv_bfloat16 lb = __float2bfloat16(f - fh);
        g_xc[i] = (unsigned)__bfloat16_as_ushort(hb)
                | ((unsigned)__bfloat16_as_ushort(lb) << 16);
    }
}

__global__ void wprep_kernel(const float* __restrict__ Wm) {
    int i = blockIdx.x * blockDim.x + threadIdx.x;
    if (i < OC_ * KDIM) {
        float f = Wm[i];
        __nv_bfloat16 hb = __float2bfloat16(f);
        float fh = __bfloat162float(hb);
        __nv_bfloat16 lb = __float2bfloat16(f - fh);
        unsigned hi = __bfloat16_as_ushort(hb);
        unsigned lo = __bfloat16_as_ushort(lb);
        g_wb1[i] = hi | (hi << 16);
        g_wb2[i] = lo;
    }
}

// ---- helpers ----
__device__ __forceinline__ unsigned smem_u32(const void* p) {
    return (unsigned)__cvta_generic_to_shared(p);
}
__device__ __forceinline__ unsigned sw128(unsigned off) {
    return off ^ ((off >> 3) & 0x70);
}
__device__ __forceinline__ void cpa4_zfill(unsigned dst, const void* src, bool pred) {
    asm volatile("cp.async.ca.shared.global [%0], [%1], 4, %2;\n"
                 :: "r"(dst), "l"(src), "r"(pred ? 4 : 0));
}
__device__ __forceinline__ void cpa16(unsigned dst, const void* src) {
    asm volatile("cp.async.cg.shared.global [%0], [%1], 16;\n"
                 :: "r"(dst), "l"(src));
}
__device__ __forceinline__ void ldsm4(unsigned* r, unsigned addr) {
    asm volatile("ldmatrix.sync.aligned.m8n8.x4.shared.b16 {%0,%1,%2,%3}, [%4];"
                 : "=r"(r[0]), "=r"(r[1]), "=r"(r[2]), "=r"(r[3]) : "r"(addr));
}
__device__ __forceinline__ void mma16816(float* c, const unsigned* a,
                                         unsigned b0, unsigned b1) {
    asm volatile(
        "mma.sync.aligned.m16n8k16.row.col.f32.bf16.bf16.f32 "
        "{%0,%1,%2,%3}, {%4,%5,%6,%7}, {%8,%9}, {%0,%1,%2,%3};"
        : "+f"(c[0]), "+f"(c[1]), "+f"(c[2]), "+f"(c[3])
        : "r"(a[0]), "r"(a[1]), "r"(a[2]), "r"(a[3]), "r"(b0), "r"(b1));
}

// ---- smem layout (bytes) ----
#define SM_BIAS 0
#define SM_TILE 1024
#define T_A     0                // 256 pix * 128B = 32768
#define T_B1    32768            // 128 oc * 128B = 16384
#define T_B2    49152
#define STG     65536
#define SMEM_TOTAL (SM_TILE + 2 * STG)   // 132096

__global__ __launch_bounds__(NT, 1)
void conv_hmma_kernel(const float* __restrict__ bias, float* __restrict__ out) {
    extern __shared__ char smem[];
    const int tid  = threadIdx.x;
    const int lane = tid & 31;
    const int wid  = tid >> 5;
    const int m0   = blockIdx.x * BM;
    const int n0   = blockIdx.y * BN;

    if (tid < OC_) ((float*)(smem + SM_BIAS))[tid] = bias[tid];

    // producer geometry: thread -> (pixel, k-slot)
    const int pix  = tid & 255;
    const int slot = tid >> 8;            // 0..1
    const int p    = m0 + pix;
    const int bimg = p / HW_;
    const int hw   = p - bimg * HW_;
    const int h    = hw / W_;
    const int w    = hw - h * W_;
    const unsigned* xb = g_xc + (size_t)bimg * (C_ * HW_);

    auto load_stage = [&](int s) {
        char* stg = smem + SM_TILE + (s & 1) * STG;
        // A tile: im2col gather of packed words, 16 per thread
        int kg  = s * BKW + slot;
        int c   = kg / 9;
        int rem = kg - 9 * c;
#pragma unroll
        for (int j = 0; j < 16; j++) {
            int wk = slot + 2 * j;
            int kh = rem / 3;
            int kw = rem - 3 * kh;
            int ih = h + kh - 1;
            int iw = w + kw - 1;
            bool pr = ((unsigned)ih < (unsigned)H_) && ((unsigned)iw < (unsigned)W_);
            const unsigned* src = xb + c * HW_ + ih * W_ + iw;
            cpa4_zfill(smem_u32(stg + T_A + sw128((unsigned)(pix * 128 + wk * 4))), src, pr);
            rem += 2;
            if (rem >= 9) { rem -= 9; c++; }
        }
        // B tiles: contiguous 16B chunks, 4 per thread
#pragma unroll
        for (int i = 0; i < 4; i++) {
            int q  = tid + NT * i;           // 0..2047
            int t  = q >> 10;
            int r  = q & 1023;
            int oc = r >> 3;
            int ch = r & 7;
            const unsigned* src = (t ? g_wb2 : g_wb1)
                                + (size_t)(n0 + oc) * KDIM + s * BKW + ch * 4;
            cpa16(smem_u32(stg + (t ? T_B2 : T_B1) + sw128((unsigned)(oc * 128 + ch * 16))), src);
        }
        asm volatile("cp.async.commit_group;\n");
    };

    // warp tiling: 4 (M) x 4 (N) warps, warp tile 64 x 32
    const int wm = (wid & 3) * 64;
    const int wn = (wid >> 2) * 32;

    float acc[4][4][4];
#pragma unroll
    for (int a = 0; a < 4; a++)
#pragma unroll
        for (int b = 0; b < 4; b++)
#pragma unroll
            for (int cq = 0; cq < 4; cq++) acc[a][b][cq] = 0.0f;

    load_stage(0);

    for (int s = 0; s < NSTAGE; s++) {
        if (s + 1 < NSTAGE) {
            load_stage(s + 1);
            asm volatile("cp.async.wait_group 1;\n");
        } else {
            asm volatile("cp.async.wait_group 0;\n");
        }
        __syncthreads();

        char* stg = smem + SM_TILE + (s & 1) * STG;
        const unsigned abase  = smem_u32(stg + T_A);
        const unsigned b1base = smem_u32(stg + T_B1);
        const unsigned b2base = smem_u32(stg + T_B2);

#pragma unroll
        for (int kk = 0; kk < 4; kk++) {
            unsigned afr[4][4];
#pragma unroll
            for (int mi = 0; mi < 4; mi++) {
                int row = wm + mi * 16 + (lane & 15);
                unsigned off = (unsigned)(row * 128 + kk * 32 + (lane >> 4) * 16);
                ldsm4(afr[mi], abase + sw128(off));
            }
#pragma unroll
            for (int t = 0; t < 2; t++) {
                const unsigned bbase = t ? b2base : b1base;
#pragma unroll
                for (int pr2 = 0; pr2 < 2; pr2++) {
                    unsigned bfr[4];
                    int g   = lane >> 3;
                    int r   = lane & 7;
                    int ocl = wn + pr2 * 16 + ((g & 2) ? 8 : 0) + r;
                    unsigned off = (unsigned)(ocl * 128 + kk * 32 + (g & 1) * 16);
                    ldsm4(bfr, bbase + sw128(off));   // NO .trans: smem [oc][k'] == B^T already
#pragma unroll
                    for (int mi = 0; mi < 4; mi++) {
                        mma16816(acc[mi][pr2 * 2 + 0], afr[mi], bfr[0], bfr[1]);
                        mma16816(acc[mi][pr2 * 2 + 1], afr[mi], bfr[2], bfr[3]);
                    }
                }
            }
        }
        __syncthreads();
    }

    // ---- epilogue: transpose through smem, coalesced float4 stores ----
    float* Cs = (float*)(smem + SM_TILE);   // [oc 128][pix 256]
#pragma unroll
    for (int mi = 0; mi < 4; mi++)
#pragma unroll
        for (int ni = 0; ni < 4; ni++) {
            int r0 = wm + mi * 16 + (lane >> 2);
            int cb = wn + ni * 8 + (lane & 3) * 2;
            Cs[(cb + 0) * BM + r0]     = acc[mi][ni][0];
            Cs[(cb + 1) * BM + r0]     = acc[mi][ni][1];
            Cs[(cb + 0) * BM + r0 + 8] = acc[mi][ni][2];
            Cs[(cb + 1) * BM + r0 + 8] = acc[mi][ni][3];
        }
    __syncthreads();

    const float* bs = (const float*)(smem + SM_BIAS);
    for (int g = tid; g < BN * (BM / 4); g += NT) {     // 128 oc * 64 groups
        int ocl  = g >> 6;
        int pixl = (g & 63) * 4;
        int pp   = m0 + pixl;
        int bi   = pp / HW_;
        int off  = pp - bi * HW_;
        int oc   = n0 + ocl;
        float4 v = *(const float4*)&Cs[ocl * BM + pixl];
        float bv = bs[oc];
        v.x += bv; v.y += bv; v.z += bv; v.w += bv;
        *(float4*)(out + (size_t)bi * OC_ * HW_ + (size_t)oc * HW_ + off) = v;
    }
}

extern "C" void kernel_launch(void* const* d_in, const int* in_sizes, int n_in,
                              void* d_out, int out_size) {
    const float* x  = (const float*)d_in[0];
    const float* Wm = (const float*)d_in[1];
    const float* bb = (const float*)d_in[2];
    float* out      = (float*)d_out;

    xprep_kernel<<<(NX_ + 255) / 256, 256>>>(x);
    wprep_kernel<<<(OC_ * KDIM + 255) / 256, 256>>>(Wm);

    cudaFuncSetAttribute(conv_hmma_kernel,
                         cudaFuncAttributeMaxDynamicSharedMemorySize, SMEM_TOTAL);
    dim3 grid(M_ / BM, OC_ / BN);   // 392 x 2
    conv_hmma_kernel<<<grid, NT, SMEM_TOTAL>>>(bb, out);
}

// round 5
// speedup vs baseline: 1.5705x; 1.0925x over previous
#include <cuda_runtime.h>
#include <cuda_bf16.h>
#include <cstdint>

#define B_    32
#define C_    128
#define H_    56
#define W_    56
#define OC_   256
#define HW_   (H_ * W_)          // 3136
#define KDIM  1152               // C*9
#define M_    (B_ * HW_)         // 100352
#define NX_   (B_ * C_ * HW_)    // 12845056

#define BM    256
#define BN    128
#define BKW   32                 // original-k words per stage (64 interleaved bf16)
#define NSTAGE 36                // 1152/32
#define NT    256                // 8 warps

// ---- static device scratch ----
__device__ __align__(16) unsigned g_xc[NX_];          // packed (hi | lo<<16) per x elem
__device__ __align__(16) unsigned g_wb1[OC_ * KDIM];  // (b_hi | b_hi<<16)
__device__ __align__(16) unsigned g_wb2[OC_ * KDIM];  // (b_lo | 0<<16)

__device__ __forceinline__ unsigned pack_split(float f) {
    __nv_bfloat16 hb = __float2bfloat16(f);
    float fh = __bfloat162float(hb);
    __nv_bfloat16 lb = __float2bfloat16(f - fh);
    return (unsigned)__bfloat16_as_ushort(hb)
         | ((unsigned)__bfloat16_as_ushort(lb) << 16);
}

__global__ void xprep_kernel(const float4* __restrict__ x4) {
    int i = blockIdx.x * blockDim.x + threadIdx.x;   // over NX_/4
    if (i < NX_ / 4) {
        float4 f = x4[i];
        uint4 o;
        o.x = pack_split(f.x); o.y = pack_split(f.y);
        o.z = pack_split(f.z); o.w = pack_split(f.w);
        ((uint4*)g_xc)[i] = o;
    }
}

__global__ void wprep_kernel(const float* __restrict__ Wm) {
    int i = blockIdx.x * blockDim.x + threadIdx.x;
    if (i < OC_ * KDIM) {
        float f = Wm[i];
        __nv_bfloat16 hb = __float2bfloat16(f);
        float fh = __bfloat162float(hb);
        __nv_bfloat16 lb = __float2bfloat16(f - fh);
        unsigned hi = __bfloat16_as_ushort(hb);
        unsigned lo = __bfloat16_as_ushort(lb);
        g_wb1[i] = hi | (hi << 16);
        g_wb2[i] = lo;
    }
}

// ---- helpers ----
__device__ __forceinline__ unsigned smem_u32(const void* p) {
    return (unsigned)__cvta_generic_to_shared(p);
}
__device__ __forceinline__ unsigned sw128(unsigned off) {
    return off ^ ((off >> 3) & 0x70);
}
__device__ __forceinline__ void cpa4_zfill(unsigned dst, const void* src, bool pred) {
    asm volatile("cp.async.ca.shared.global [%0], [%1], 4, %2;\n"
                 :: "r"(dst), "l"(src), "r"(pred ? 4 : 0));
}
__device__ __forceinline__ void cpa16(unsigned dst, const void* src) {
    asm volatile("cp.async.cg.shared.global [%0], [%1], 16;\n"
                 :: "r"(dst), "l"(src));
}
__device__ __forceinline__ void ldsm4(unsigned* r, unsigned addr) {
    asm volatile("ldmatrix.sync.aligned.m8n8.x4.shared.b16 {%0,%1,%2,%3}, [%4];"
                 : "=r"(r[0]), "=r"(r[1]), "=r"(r[2]), "=r"(r[3]) : "r"(addr));
}
__device__ __forceinline__ void mma16816(float* c, const unsigned* a,
                                         unsigned b0, unsigned b1) {
    asm volatile(
        "mma.sync.aligned.m16n8k16.row.col.f32.bf16.bf16.f32 "
        "{%0,%1,%2,%3}, {%4,%5,%6,%7}, {%8,%9}, {%0,%1,%2,%3};"
        : "+f"(c[0]), "+f"(c[1]), "+f"(c[2]), "+f"(c[3])
        : "r"(a[0]), "r"(a[1]), "r"(a[2]), "r"(a[3]), "r"(b0), "r"(b1));
}

// ---- smem layout (bytes) ----
#define SM_BIAS 0
#define SM_TILE 1024
#define T_A     0                // 256 pix * 128B = 32768
#define T_B1    32768            // 128 oc * 128B = 16384
#define T_B2    49152
#define STG     65536
#define SMEM_TOTAL (SM_TILE + 3 * STG)   // 197632

__global__ __launch_bounds__(NT, 1)
void conv_hmma_kernel(const float* __restrict__ bias, float* __restrict__ out) {
    extern __shared__ char smem[];
    const int tid  = threadIdx.x;
    const int lane = tid & 31;
    const int wid  = tid >> 5;
    const int m0   = blockIdx.x * BM;
    const int n0   = blockIdx.y * BN;

    ((float*)(smem + SM_BIAS))[tid] = bias[tid];   // NT == OC_

    // producer geometry: one pixel per thread, all 32 k-words
    const int pix  = tid;
    const int p    = m0 + pix;
    const int bimg = p / HW_;
    const int hw   = p - bimg * HW_;
    const int h    = hw / W_;
    const int w    = hw - h * W_;
    const unsigned* xb = g_xc + (size_t)bimg * (C_ * HW_);

    auto load_stage = [&](int s, int slot) {
        char* stg = smem + SM_TILE + slot * STG;
        // A tile: im2col gather of packed words, 32 per thread (one pixel)
        int kg  = s * BKW;
        int c   = kg / 9;
        int rem = kg - 9 * c;
#pragma unroll
        for (int wk = 0; wk < BKW; wk++) {
            int kh = rem / 3;
            int kw = rem - 3 * kh;
            int ih = h + kh - 1;
            int iw = w + kw - 1;
            bool pr = ((unsigned)ih < (unsigned)H_) && ((unsigned)iw < (unsigned)W_);
            const unsigned* src = xb + c * HW_ + ih * W_ + iw;
            cpa4_zfill(smem_u32(stg + T_A + sw128((unsigned)(pix * 128 + wk * 4))), src, pr);
            if (++rem == 9) { rem = 0; c++; }
        }
        // B tiles: contiguous 16B chunks, 8 per thread
#pragma unroll
        for (int i = 0; i < 8; i++) {
            int q  = tid + NT * i;           // 0..2047
            int t  = q >> 10;
            int r  = q & 1023;
            int oc = r >> 3;
            int ch = r & 7;
            const unsigned* src = (t ? g_wb2 : g_wb1)
                                + (size_t)(n0 + oc) * KDIM + s * BKW + ch * 4;
            cpa16(smem_u32(stg + (t ? T_B2 : T_B1) + sw128((unsigned)(oc * 128 + ch * 16))), src);
        }
        asm volatile("cp.async.commit_group;\n");
    };

    // warp tiling: 4 (M) x 2 (N) warps, warp tile 64 x 64
    const int wm = (wid & 3) * 64;
    const int wn = (wid >> 2) * 64;

    float acc[4][8][4];
#pragma unroll
    for (int a = 0; a < 4; a++)
#pragma unroll
        for (int b = 0; b < 8; b++)
#pragma unroll
            for (int cq = 0; cq < 4; cq++) acc[a][b][cq] = 0.0f;

    load_stage(0, 0);
    load_stage(1, 1);

    int slot = 0, slot2 = 2;    // slot of s, slot of s+2
    for (int s = 0; s < NSTAGE; s++) {
        asm volatile("cp.async.wait_group 1;\n");
        __syncthreads();

        char* stg = smem + SM_TILE + slot * STG;
        const unsigned abase  = smem_u32(stg + T_A);
        const unsigned b1base = smem_u32(stg + T_B1);
        const unsigned b2base = smem_u32(stg + T_B2);

#pragma unroll
        for (int kk = 0; kk < 4; kk++) {
            unsigned afr[4][4];
#pragma unroll
            for (int mi = 0; mi < 4; mi++) {
                int row = wm + mi * 16 + (lane & 15);
                unsigned off = (unsigned)(row * 128 + kk * 32 + (lane >> 4) * 16);
                ldsm4(afr[mi], abase + sw128(off));
            }
#pragma unroll
            for (int t = 0; t < 2; t++) {
                const unsigned bbase = t ? b2base : b1base;
#pragma unroll
                for (int ni = 0; ni < 4; ni++) {       // 16 oc per ldsm4
                    unsigned bfr[4];
                    int g   = lane >> 3;
                    int r   = lane & 7;
                    int ocl = wn + ni * 16 + ((g & 2) ? 8 : 0) + r;
                    unsigned off = (unsigned)(ocl * 128 + kk * 32 + (g & 1) * 16);
                    ldsm4(bfr, bbase + sw128(off));
#pragma unroll
                    for (int mi = 0; mi < 4; mi++) {
                        mma16816(acc[mi][ni * 2 + 0], afr[mi], bfr[0], bfr[1]);
                        mma16816(acc[mi][ni * 2 + 1], afr[mi], bfr[2], bfr[3]);
                    }
                }
            }
        }

        if (s + 2 < NSTAGE) load_stage(s + 2, slot2);
        else asm volatile("cp.async.commit_group;\n");

        slot  = (slot  == 2) ? 0 : slot  + 1;
        slot2 = (slot2 == 2) ? 0 : slot2 + 1;
    }

    __syncthreads();

    // ---- epilogue: transpose through smem, coalesced float4 stores ----
    float* Cs = (float*)(smem + SM_TILE);   // [oc 128][pix 256] = 128KB
#pragma unroll
    for (int mi = 0; mi < 4; mi++)
#pragma unroll
        for (int ni = 0; ni < 8; ni++) {
            int r0 = wm + mi * 16 + (lane >> 2);
            int cb = wn + ni * 8 + (lane & 3) * 2;
            Cs[(cb + 0) * BM + r0]     = acc[mi][ni][0];
            Cs[(cb + 1) * BM + r0]     = acc[mi][ni][1];
            Cs[(cb + 0) * BM + r0 + 8] = acc[mi][ni][2];
            Cs[(cb + 1) * BM + r0 + 8] = acc[mi][ni][3];
        }
    __syncthreads();

    const float* bs = (const float*)(smem + SM_BIAS);
    for (int g = tid; g < BN * (BM / 4); g += NT) {     // 128 oc * 64 groups
        int ocl  = g >> 6;
        int pixl = (g & 63) * 4;
        int pp   = m0 + pixl;
        int bi   = pp / HW_;
        int off  = pp - bi * HW_;
        int oc   = n0 + ocl;
        float4 v = *(const float4*)&Cs[ocl * BM + pixl];
        float bv = bs[oc];
        v.x += bv; v.y += bv; v.z += bv; v.w += bv;
        *(float4*)(out + (size_t)bi * OC_ * HW_ + (size_t)oc * HW_ + off) = v;
    }
}

extern "C" void kernel_launch(void* const* d_in, const int* in_sizes, int n_in,
                              void* d_out, int out_size) {
    const float* x  = (const float*)d_in[0];
    const float* Wm = (const float*)d_in[1];
    const float* bb = (const float*)d_in[2];
    float* out      = (float*)d_out;

    xprep_kernel<<<(NX_ / 4 + 255) / 256, 256>>>((const float4*)x);
    wprep_kernel<<<(OC_ * KDIM + 255) / 256, 256>>>(Wm);

    cudaFuncSetAttribute(conv_hmma_kernel,
                         cudaFuncAttributeMaxDynamicSharedMemorySize, SMEM_TOTAL);
    dim3 grid(M_ / BM, OC_ / BN);   // 392 x 2
    conv_hmma_kernel<<<grid, NT, SMEM_TOTAL>>>(bb, out);
}

// round 6
// speedup vs baseline: 1.6836x; 1.0720x over previous
#include <cuda_runtime.h>
#include <cuda_bf16.h>
#include <cstdint>

#define B_    32
#define C_    128
#define H_    56
#define W_    56
#define OC_   256
#define HW_   (H_ * W_)          // 3136
#define KDIM  1152               // C*9
#define M_    (B_ * HW_)         // 100352
#define NX_   (B_ * C_ * HW_)    // 12845056

#define BM    256
#define BN    128
#define BKW   32                 // original-k per stage (64 interleaved k')
#define NSTAGE 36                // 1152/32
#define NT    256                // 8 warps

// ---- static device scratch ----
__device__ __align__(16) unsigned g_xc[NX_];         // (a_lo | a_hi<<16) per x elem
__device__ __align__(16) unsigned g_wi[OC_ * KDIM];  // (b_hi | b_lo<<16)

__device__ __forceinline__ unsigned pack_x(float f) {
    __nv_bfloat16 hb = __float2bfloat16(f);
    float fh = __bfloat162float(hb);
    __nv_bfloat16 lb = __float2bfloat16(f - fh);
    return (unsigned)__bfloat16_as_ushort(lb)
         | ((unsigned)__bfloat16_as_ushort(hb) << 16);   // (lo | hi<<16)
}

__global__ void xprep_kernel(const float4* __restrict__ x4) {
    int i = blockIdx.x * blockDim.x + threadIdx.x;   // over NX_/4
    if (i < NX_ / 4) {
        float4 f = x4[i];
        uint4 o;
        o.x = pack_x(f.x); o.y = pack_x(f.y);
        o.z = pack_x(f.z); o.w = pack_x(f.w);
        ((uint4*)g_xc)[i] = o;
    }
}

__global__ void wprep_kernel(const float* __restrict__ Wm) {
    int i = blockIdx.x * blockDim.x + threadIdx.x;
    if (i < OC_ * KDIM) {
        float f = Wm[i];
        __nv_bfloat16 hb = __float2bfloat16(f);
        float fh = __bfloat162float(hb);
        __nv_bfloat16 lb = __float2bfloat16(f - fh);
        g_wi[i] = (unsigned)__bfloat16_as_ushort(hb)
                | ((unsigned)__bfloat16_as_ushort(lb) << 16);   // (hi | lo<<16)
    }
}

// ---- helpers ----
__device__ __forceinline__ unsigned smem_u32(const void* p) {
    return (unsigned)__cvta_generic_to_shared(p);
}
__device__ __forceinline__ unsigned sw128(unsigned off) {
    return off ^ ((off >> 3) & 0x70);
}
__device__ __forceinline__ void cpa4_zfill(unsigned dst, const void* src, bool pred) {
    asm volatile("cp.async.ca.shared.global [%0], [%1], 4, %2;\n"
                 :: "r"(dst), "l"(src), "r"(pred ? 4 : 0));
}
__device__ __forceinline__ void cpa16(unsigned dst, const void* src) {
    asm volatile("cp.async.cg.shared.global [%0], [%1], 16;\n"
                 :: "r"(dst), "l"(src));
}
__device__ __forceinline__ void ldsm4(unsigned* r, unsigned addr) {
    asm volatile("ldmatrix.sync.aligned.m8n8.x4.shared.b16 {%0,%1,%2,%3}, [%4];"
                 : "=r"(r[0]), "=r"(r[1]), "=r"(r[2]), "=r"(r[3]) : "r"(addr));
}
__device__ __forceinline__ void mma16816(float* c, const unsigned* a,
                                         unsigned b0, unsigned b1) {
    asm volatile(
        "mma.sync.aligned.m16n8k16.row.col.f32.bf16.bf16.f32 "
        "{%0,%1,%2,%3}, {%4,%5,%6,%7}, {%8,%9}, {%0,%1,%2,%3};"
        : "+f"(c[0]), "+f"(c[1]), "+f"(c[2]), "+f"(c[3])
        : "r"(a[0]), "r"(a[1]), "r"(a[2]), "r"(a[3]), "r"(b0), "r"(b1));
}

// ---- smem layout (bytes) ----
#define SM_BIAS 0
#define SM_TILE 1024
#define T_A     0                // 256 pix * 128B = 32768
#define T_B     32768            // 128 oc * 128B = 16384
#define STG     49152
#define SMEM_TOTAL (SM_TILE + 3 * STG)   // 148480

__global__ __launch_bounds__(NT, 1)
void conv_hmma_kernel(const float* __restrict__ bias, float* __restrict__ out) {
    extern __shared__ char smem[];
    const int tid  = threadIdx.x;
    const int lane = tid & 31;
    const int wid  = tid >> 5;
    const int m0   = blockIdx.x * BM;
    const int n0   = blockIdx.y * BN;

    ((float*)(smem + SM_BIAS))[tid] = bias[tid];   // NT == OC_

    // producer geometry: one pixel per thread, all 32 k-words
    const int pix  = tid;
    const int p    = m0 + pix;
    const int bimg = p / HW_;
    const int hw   = p - bimg * HW_;
    const int h    = hw / W_;
    const int w    = hw - h * W_;
    const unsigned* xb = g_xc + (size_t)bimg * (C_ * HW_);

    auto load_stage = [&](int s, int slot) {
        char* stg = smem + SM_TILE + slot * STG;
        // A tile: im2col gather of packed (lo|hi) words, 32 per thread
        int kg  = s * BKW;
        int c   = kg / 9;
        int rem = kg - 9 * c;
#pragma unroll
        for (int wk = 0; wk < BKW; wk++) {
            int kh = rem / 3;
            int kw = rem - 3 * kh;
            int ih = h + kh - 1;
            int iw = w + kw - 1;
            bool pr = ((unsigned)ih < (unsigned)H_) && ((unsigned)iw < (unsigned)W_);
            const unsigned* src = xb + c * HW_ + ih * W_ + iw;
            cpa4_zfill(smem_u32(stg + T_A + sw128((unsigned)(pix * 128 + wk * 4))), src, pr);
            if (++rem == 9) { rem = 0; c++; }
        }
        // B tile: contiguous 16B chunks, 4 per thread (1024 total)
#pragma unroll
        for (int i = 0; i < 4; i++) {
            int q  = tid + NT * i;           // 0..1023
            int oc = q >> 3;
            int ch = q & 7;
            const unsigned* src = g_wi + (size_t)(n0 + oc) * KDIM + s * BKW + ch * 4;
            cpa16(smem_u32(stg + T_B + sw128((unsigned)(oc * 128 + ch * 16))), src);
        }
        asm volatile("cp.async.commit_group;\n");
    };

    // warp tiling: 4 (M) x 2 (N) warps, warp tile 64 x 64
    const int wm = (wid & 3) * 64;
    const int wn = (wid >> 2) * 64;

    float acc[4][8][4];
#pragma unroll
    for (int a = 0; a < 4; a++)
#pragma unroll
        for (int b = 0; b < 8; b++)
#pragma unroll
            for (int cq = 0; cq < 4; cq++) acc[a][b][cq] = 0.0f;

    load_stage(0, 0);
    load_stage(1, 1);

    int slot = 0, slot2 = 2;    // slot of s, slot of s+2
    for (int s = 0; s < NSTAGE; s++) {
        asm volatile("cp.async.wait_group 1;\n");
        __syncthreads();

        if (s + 2 < NSTAGE) load_stage(s + 2, slot2);
        else asm volatile("cp.async.commit_group;\n");

        char* stg = smem + SM_TILE + slot * STG;
        const unsigned abase = smem_u32(stg + T_A);
        const unsigned bbase = smem_u32(stg + T_B);

#pragma unroll
        for (int pp = 0; pp < 2; pp++) {        // pair of 16-k' chunks
            unsigned afrE[4][4], afrO[4][4];
#pragma unroll
            for (int mi = 0; mi < 4; mi++) {
                int row = wm + mi * 16 + (lane & 15);
                unsigned base = (unsigned)(row * 128 + (lane >> 4) * 16);
                ldsm4(afrE[mi], abase + sw128(base + (2 * pp + 0) * 32));
                ldsm4(afrO[mi], abase + sw128(base + (2 * pp + 1) * 32));
            }
            // synthesize pure-hi A fragments (hi = bytes 2,3 of (lo|hi) word)
            unsigned ahi[4][4];
#pragma unroll
            for (int mi = 0; mi < 4; mi++) {
                ahi[mi][0] = __byte_perm(afrE[mi][0], afrE[mi][2], 0x7632);
                ahi[mi][1] = __byte_perm(afrE[mi][1], afrE[mi][3], 0x7632);
                ahi[mi][2] = __byte_perm(afrO[mi][0], afrO[mi][2], 0x7632);
                ahi[mi][3] = __byte_perm(afrO[mi][1], afrO[mi][3], 0x7632);
            }
#pragma unroll
            for (int ni = 0; ni < 4; ni++) {
                unsigned bE[4], bO[4];
                int g   = lane >> 3;
                int r   = lane & 7;
                int ocl = wn + ni * 16 + ((g & 2) ? 8 : 0) + r;
                unsigned base = (unsigned)(ocl * 128 + (g & 1) * 16);
                ldsm4(bE, bbase + sw128(base + (2 * pp + 0) * 32));
                ldsm4(bO, bbase + sw128(base + (2 * pp + 1) * 32));
                // pass 2: interleaved corrections (a_lo*b_hi + a_hi*b_lo)
#pragma unroll
                for (int mi = 0; mi < 4; mi++) {
                    mma16816(acc[mi][ni * 2 + 0], afrE[mi], bE[0], bE[1]);
                    mma16816(acc[mi][ni * 2 + 1], afrE[mi], bE[2], bE[3]);
                    mma16816(acc[mi][ni * 2 + 0], afrO[mi], bO[0], bO[1]);
                    mma16816(acc[mi][ni * 2 + 1], afrO[mi], bO[2], bO[3]);
                }
                // pass 1: main hi*hi term (hi = bytes 0,1 of (hi|lo) word)
                unsigned bh0 = __byte_perm(bE[0], bE[1], 0x5410);
                unsigned bh1 = __byte_perm(bO[0], bO[1], 0x5410);
                unsigned bh2 = __byte_perm(bE[2], bE[3], 0x5410);
                unsigned bh3 = __byte_perm(bO[2], bO[3], 0x5410);
#pragma unroll
                for (int mi = 0; mi < 4; mi++) {
                    mma16816(acc[mi][ni * 2 + 0], ahi[mi], bh0, bh1);
                    mma16816(acc[mi][ni * 2 + 1], ahi[mi], bh2, bh3);
                }
            }
        }

        slot  = (slot  == 2) ? 0 : slot  + 1;
        slot2 = (slot2 == 2) ? 0 : slot2 + 1;
    }

    __syncthreads();

    // ---- epilogue: transpose through smem, coalesced float4 stores ----
    float* Cs = (float*)(smem + SM_TILE);   // [oc 128][pix 256] = 128KB
#pragma unroll
    for (int mi = 0; mi < 4; mi++)
#pragma unroll
        for (int ni = 0; ni < 8; ni++) {
            int r0 = wm + mi * 16 + (lane >> 2);
            int cb = wn + ni * 8 + (lane & 3) * 2;
            Cs[(cb + 0) * BM + r0]     = acc[mi][ni][0];
            Cs[(cb + 1) * BM + r0]     = acc[mi][ni][1];
            Cs[(cb + 0) * BM + r0 + 8] = acc[mi][ni][2];
            Cs[(cb + 1) * BM + r0 + 8] = acc[mi][ni][3];
        }
    __syncthreads();

    const float* bs = (const float*)(smem + SM_BIAS);
    for (int g = tid; g < BN * (BM / 4); g += NT) {     // 128 oc * 64 groups
        int ocl  = g >> 6;
        int pixl = (g & 63) * 4;
        int pp   = m0 + pixl;
        int bi   = pp / HW_;
        int off  = pp - bi * HW_;
        int oc   = n0 + ocl;
        float4 v = *(const float4*)&Cs[ocl * BM + pixl];
        float bv = bs[oc];
        v.x += bv; v.y += bv; v.z += bv; v.w += bv;
        *(float4*)(out + (size_t)bi * OC_ * HW_ + (size_t)oc * HW_ + off) = v;
    }
}

extern "C" void kernel_launch(void* const* d_in, const int* in_sizes, int n_in,
                              void* d_out, int out_size) {
    const float* x  = (const float*)d_in[0];
    const float* Wm = (const float*)d_in[1];
    const float* bb = (const float*)d_in[2];
    float* out      = (float*)d_out;

    xprep_kernel<<<(NX_ / 4 + 255) / 256, 256>>>((const float4*)x);
    wprep_kernel<<<(OC_ * KDIM + 255) / 256, 256>>>(Wm);

    cudaFuncSetAttribute(conv_hmma_kernel,
                         cudaFuncAttributeMaxDynamicSharedMemorySize, SMEM_TOTAL);
    dim3 grid(M_ / BM, OC_ / BN);   // 392 x 2
    conv_hmma_kernel<<<grid, NT, SMEM_TOTAL>>>(bb, out);
}

// round 7
// speedup vs baseline: 1.9721x; 1.1713x over previous
#include <cuda_runtime.h>
#include <cuda_bf16.h>
#include <cstdint>

#define B_    32
#define C_    128
#define H_    56
#define W_    56
#define OC_   256
#define HW_   (H_ * W_)          // 3136
#define KDIM  1152               // C*9
#define M_    (B_ * HW_)         // 100352
#define NX_   (B_ * C_ * HW_)    // 12845056
#define NW_   (OC_ * KDIM)       // 294912

#define BM    128
#define BN    128
#define BKW   32                 // original-k per stage (64 interleaved k')
#define NSTAGE 36                // 1152/32
#define NT    256                // 8 warps

// ---- static device scratch ----
__device__ __align__(16) unsigned g_xc[NX_];   // (a_lo | a_hi<<16) per x elem
__device__ __align__(16) unsigned g_wi[NW_];   // (b_hi | b_lo<<16)

__device__ __forceinline__ unsigned pack_x(float f) {
    __nv_bfloat16 hb = __float2bfloat16(f);
    float fh = __bfloat162float(hb);
    __nv_bfloat16 lb = __float2bfloat16(f - fh);
    return (unsigned)__bfloat16_as_ushort(lb)
         | ((unsigned)__bfloat16_as_ushort(hb) << 16);   // (lo | hi<<16)
}

// merged prep: x-part (vectorized) then w-part — 2 launches/replay total
__global__ void prep_kernel(const float4* __restrict__ x4,
                            const float* __restrict__ Wm) {
    int i = blockIdx.x * blockDim.x + threadIdx.x;
    if (i < NX_ / 4) {
        float4 f = x4[i];
        uint4 o;
        o.x = pack_x(f.x); o.y = pack_x(f.y);
        o.z = pack_x(f.z); o.w = pack_x(f.w);
        ((uint4*)g_xc)[i] = o;
    } else {
        int j = i - NX_ / 4;
        if (j < NW_) {
            float f = Wm[j];
            __nv_bfloat16 hb = __float2bfloat16(f);
            float fh = __bfloat162float(hb);
            __nv_bfloat16 lb = __float2bfloat16(f - fh);
            g_wi[j] = (unsigned)__bfloat16_as_ushort(hb)
                    | ((unsigned)__bfloat16_as_ushort(lb) << 16);   // (hi | lo<<16)
        }
    }
}

// ---- helpers ----
__device__ __forceinline__ unsigned smem_u32(const void* p) {
    return (unsigned)__cvta_generic_to_shared(p);
}
__device__ __forceinline__ unsigned sw128(unsigned off) {
    return off ^ ((off >> 3) & 0x70);
}
__device__ __forceinline__ void cpa4_zfill(unsigned dst, const void* src, bool pred) {
    asm volatile("cp.async.ca.shared.global [%0], [%1], 4, %2;\n"
                 :: "r"(dst), "l"(src), "r"(pred ? 4 : 0));
}
__device__ __forceinline__ void cpa16(unsigned dst, const void* src) {
    asm volatile("cp.async.cg.shared.global [%0], [%1], 16;\n"
                 :: "r"(dst), "l"(src));
}
__device__ __forceinline__ void ldsm4(unsigned* r, unsigned addr) {
    asm volatile("ldmatrix.sync.aligned.m8n8.x4.shared.b16 {%0,%1,%2,%3}, [%4];"
                 : "=r"(r[0]), "=r"(r[1]), "=r"(r[2]), "=r"(r[3]) : "r"(addr));
}
__device__ __forceinline__ void mma16816(float* c, const unsigned* a,
                                         unsigned b0, unsigned b1) {
    asm volatile(
        "mma.sync.aligned.m16n8k16.row.col.f32.bf16.bf16.f32 "
        "{%0,%1,%2,%3}, {%4,%5,%6,%7}, {%8,%9}, {%0,%1,%2,%3};"
        : "+f"(c[0]), "+f"(c[1]), "+f"(c[2]), "+f"(c[3])
        : "r"(a[0]), "r"(a[1]), "r"(a[2]), "r"(a[3]), "r"(b0), "r"(b1));
}

// ---- smem layout (bytes) ----
#define SM_BIAS 0
#define SM_TILE 1024
#define T_A     0                // 128 pix * 128B = 16384
#define T_B     16384            // 128 oc * 128B = 16384
#define STG     32768
#define SMEM_TOTAL (SM_TILE + 3 * STG)   // 99328  -> 2 CTAs/SM

__global__ __launch_bounds__(NT, 2)
void conv_hmma_kernel(const float* __restrict__ bias, float* __restrict__ out) {
    extern __shared__ char smem[];
    const int tid  = threadIdx.x;
    const int lane = tid & 31;
    const int wid  = tid >> 5;
    const int m0   = blockIdx.x * BM;
    const int n0   = blockIdx.y * BN;

    if (tid < OC_) ((float*)(smem + SM_BIAS))[tid] = bias[tid];

    // producer geometry: pix = tid&127, 16 k-words per thread
    const int pix  = tid & 127;
    const int half = tid >> 7;            // 0..1
    const int p    = m0 + pix;
    const int bimg = p / HW_;
    const int hw   = p - bimg * HW_;
    const int h    = hw / W_;
    const int w    = hw - h * W_;
    const unsigned* xb = g_xc + (size_t)bimg * (C_ * HW_);

    auto load_stage = [&](int s, int slot) {
        char* stg = smem + SM_TILE + slot * STG;
        // A tile: im2col gather of packed (lo|hi) words
        int kg  = s * BKW + half;
        int c   = kg / 9;
        int rem = kg - 9 * c;
#pragma unroll
        for (int j = 0; j < 16; j++) {
            int wk = half + 2 * j;
            int kh = rem / 3;
            int kw = rem - 3 * kh;
            int ih = h + kh - 1;
            int iw = w + kw - 1;
            bool pr = ((unsigned)ih < (unsigned)H_) && ((unsigned)iw < (unsigned)W_);
            const unsigned* src = xb + c * HW_ + ih * W_ + iw;
            cpa4_zfill(smem_u32(stg + T_A + sw128((unsigned)(pix * 128 + wk * 4))), src, pr);
            rem += 2;
            if (rem >= 9) { rem -= 9; c++; }
        }
        // B tile: contiguous 16B chunks, 4 per thread (1024 total)
#pragma unroll
        for (int i = 0; i < 4; i++) {
            int q  = tid + NT * i;           // 0..1023
            int oc = q >> 3;                 // 0..127
            int ch = q & 7;
            const unsigned* src = g_wi + (size_t)(n0 + oc) * KDIM + s * BKW + ch * 4;
            cpa16(smem_u32(stg + T_B + sw128((unsigned)(oc * 128 + ch * 16))), src);
        }
        asm volatile("cp.async.commit_group;\n");
    };

    // warp tiling: 2 (M) x 4 (N) warps, warp tile 64 x 32
    const int wm = (wid & 1) * 64;
    const int wn = (wid >> 1) * 32;

    float acc[4][4][4];
#pragma unroll
    for (int a = 0; a < 4; a++)
#pragma unroll
        for (int b = 0; b < 4; b++)
#pragma unroll
            for (int cq = 0; cq < 4; cq++) acc[a][b][cq] = 0.0f;

    load_stage(0, 0);
    load_stage(1, 1);

    int slot = 0, slot2 = 2;    // slot of s, slot of s+2
    for (int s = 0; s < NSTAGE; s++) {
        asm volatile("cp.async.wait_group 1;\n");
        __syncthreads();

        if (s + 2 < NSTAGE) load_stage(s + 2, slot2);
        else asm volatile("cp.async.commit_group;\n");

        char* stg = smem + SM_TILE + slot * STG;
        const unsigned abase = smem_u32(stg + T_A);
        const unsigned bbase = smem_u32(stg + T_B);

#pragma unroll
        for (int pp = 0; pp < 2; pp++) {        // pair of 16-k' chunks
            unsigned afrE[4][4], afrO[4][4];
#pragma unroll
            for (int mi = 0; mi < 4; mi++) {
                int row = wm + mi * 16 + (lane & 15);
                unsigned base = (unsigned)(row * 128 + (lane >> 4) * 16);
                ldsm4(afrE[mi], abase + sw128(base + (2 * pp + 0) * 32));
                ldsm4(afrO[mi], abase + sw128(base + (2 * pp + 1) * 32));
            }
            // synthesize pure-hi A fragments (hi = bytes 2,3 of (lo|hi) word)
            unsigned ahi[4][4];
#pragma unroll
            for (int mi = 0; mi < 4; mi++) {
                ahi[mi][0] = __byte_perm(afrE[mi][0], afrE[mi][2], 0x7632);
                ahi[mi][1] = __byte_perm(afrE[mi][1], afrE[mi][3], 0x7632);
                ahi[mi][2] = __byte_perm(afrO[mi][0], afrO[mi][2], 0x7632);
                ahi[mi][3] = __byte_perm(afrO[mi][1], afrO[mi][3], 0x7632);
            }
#pragma unroll
            for (int ni = 0; ni < 2; ni++) {       // 16 oc per ldsm4
                unsigned bE[4], bO[4];
                int g   = lane >> 3;
                int r   = lane & 7;
                int ocl = wn + ni * 16 + ((g & 2) ? 8 : 0) + r;
                unsigned base = (unsigned)(ocl * 128 + (g & 1) * 16);
                ldsm4(bE, bbase + sw128(base + (2 * pp + 0) * 32));
                ldsm4(bO, bbase + sw128(base + (2 * pp + 1) * 32));
                // pass 2: interleaved corrections (a_lo*b_hi + a_hi*b_lo)
#pragma unroll
                for (int mi = 0; mi < 4; mi++) {
                    mma16816(acc[mi][ni * 2 + 0], afrE[mi], bE[0], bE[1]);
                    mma16816(acc[mi][ni * 2 + 1], afrE[mi], bE[2], bE[3]);
                    mma16816(acc[mi][ni * 2 + 0], afrO[mi], bO[0], bO[1]);
                    mma16816(acc[mi][ni * 2 + 1], afrO[mi], bO[2], bO[3]);
                }
                // pass 1: main hi*hi term (hi = bytes 0,1 of (hi|lo) word)
                unsigned bh0 = __byte_perm(bE[0], bE[1], 0x5410);
                unsigned bh1 = __byte_perm(bO[0], bO[1], 0x5410);
                unsigned bh2 = __byte_perm(bE[2], bE[3], 0x5410);
                unsigned bh3 = __byte_perm(bO[2], bO[3], 0x5410);
#pragma unroll
                for (int mi = 0; mi < 4; mi++) {
                    mma16816(acc[mi][ni * 2 + 0], ahi[mi], bh0, bh1);
                    mma16816(acc[mi][ni * 2 + 1], ahi[mi], bh2, bh3);
                }
            }
        }

        slot  = (slot  == 2) ? 0 : slot  + 1;
        slot2 = (slot2 == 2) ? 0 : slot2 + 1;
    }

    __syncthreads();

    // ---- epilogue: transpose through smem, coalesced float4 stores ----
    float* Cs = (float*)(smem + SM_TILE);   // [oc 128][pix 128] = 64KB
#pragma unroll
    for (int mi = 0; mi < 4; mi++)
#pragma unroll
        for (int nq = 0; nq < 4; nq++) {
            int r0 = wm + mi * 16 + (lane >> 2);
            int cb = wn + nq * 8 + (lane & 3) * 2;
            Cs[(cb + 0) * BM + r0]     = acc[mi][nq][0];
            Cs[(cb + 1) * BM + r0]     = acc[mi][nq][1];
            Cs[(cb + 0) * BM + r0 + 8] = acc[mi][nq][2];
            Cs[(cb + 1) * BM + r0 + 8] = acc[mi][nq][3];
        }
    __syncthreads();

    const float* bs = (const float*)(smem + SM_BIAS);
    for (int g = tid; g < BN * (BM / 4); g += NT) {     // 128 oc * 32 groups
        int ocl  = g >> 5;
        int pixl = (g & 31) * 4;
        int pp   = m0 + pixl;
        int bi   = pp / HW_;
        int off  = pp - bi * HW_;
        int oc   = n0 + ocl;
        float4 v = *(const float4*)&Cs[ocl * BM + pixl];
        float bv = bs[oc];
        v.x += bv; v.y += bv; v.z += bv; v.w += bv;
        *(float4*)(out + (size_t)bi * OC_ * HW_ + (size_t)oc * HW_ + off) = v;
    }
}

extern "C" void kernel_launch(void* const* d_in, const int* in_sizes, int n_in,
                              void* d_out, int out_size) {
    const float* x  = (const float*)d_in[0];
    const float* Wm = (const float*)d_in[1];
    const float* bb = (const float*)d_in[2];
    float* out      = (float*)d_out;

    int total = NX_ / 4 + NW_;
    prep_kernel<<<(total + 255) / 256, 256>>>((const float4*)x, Wm);

    cudaFuncSetAttribute(conv_hmma_kernel,
                         cudaFuncAttributeMaxDynamicSharedMemorySize, SMEM_TOTAL);
    dim3 grid(M_ / BM, OC_ / BN);   // 784 x 2
    conv_hmma_kernel<<<grid, NT, SMEM_TOTAL>>>(bb, out);
}

// round 9
// speedup vs baseline: 2.2338x; 1.1327x over previous
#include <cuda_runtime.h>
#include <cuda_bf16.h>
#include <cstdint>

#define B_    32
#define C_    128
#define H_    56
#define W_    56
#define OC_   256
#define HW_   (H_ * W_)          // 3136
#define KDIM  1152               // C*9
#define M_    (B_ * HW_)         // 100352
#define NX_   (B_ * C_ * HW_)    // 12845056
#define NW_   (OC_ * KDIM)       // 294912

#define HP    58                 // padded H
#define WP    58                 // padded W
#define HWP   (HP * WP)          // 3364
#define NXP_  (B_ * C_ * HWP)    // 13787136

#define BM    128
#define BN    128
#define BKW   32                 // k' per stage (one tap, 32 channels)
#define NSTAGE 36                // 9 taps * 4 channel-chunks
#define NT    256                // 8 warps

// ---- static device scratch ----
// zero-padded packed x: (a_lo | a_hi<<16), halo stays 0 from bss zero-init
__device__ unsigned g_xp[NXP_];
// reordered packed W: [oc][tap*128 + c] = (b_hi | b_lo<<16)
__device__ __align__(16) unsigned g_wi[NW_];

__device__ __forceinline__ unsigned pack_x(float f) {
    __nv_bfloat16 hb = __float2bfloat16(f);
    float fh = __bfloat162float(hb);
    __nv_bfloat16 lb = __float2bfloat16(f - fh);
    return (unsigned)__bfloat16_as_ushort(lb)
         | ((unsigned)__bfloat16_as_ushort(hb) << 16);   // (lo | hi<<16)
}

// merged prep: pad+pack x, reorder+pack W  (2 launches per replay total)
__global__ void prep_kernel(const float* __restrict__ x,
                            const float* __restrict__ Wm) {
    int i = blockIdx.x * blockDim.x + threadIdx.x;
    if (i < NX_) {
        int bc = i / HW_;
        int r  = i - bc * HW_;
        int h  = r / W_;
        int w  = r - h * W_;
        g_xp[(bc * HP + h + 1) * WP + w + 1] = pack_x(x[i]);
    } else {
        int j = i - NX_;
        if (j < NW_) {
            int oc  = j / KDIM;
            int r   = j - oc * KDIM;
            int c   = r / 9;
            int tap = r - c * 9;
            float f = Wm[j];
            __nv_bfloat16 hb = __float2bfloat16(f);
            float fh = __bfloat162float(hb);
            __nv_bfloat16 lb = __float2bfloat16(f - fh);
            g_wi[oc * KDIM + tap * 128 + c] =
                  (unsigned)__bfloat16_as_ushort(hb)
                | ((unsigned)__bfloat16_as_ushort(lb) << 16);   // (hi | lo<<16)
        }
    }
}

// ---- helpers ----
__device__ __forceinline__ unsigned smem_u32(const void* p) {
    return (unsigned)__cvta_generic_to_shared(p);
}
__device__ __forceinline__ unsigned sw128(unsigned off) {
    return off ^ ((off >> 3) & 0x70);
}
__device__ __forceinline__ void cpa4(unsigned dst, const void* src) {
    asm volatile("cp.async.ca.shared.global [%0], [%1], 4;\n"
                 :: "r"(dst), "l"(src));
}
__device__ __forceinline__ void cpa16(unsigned dst, const void* src) {
    asm volatile("cp.async.cg.shared.global [%0], [%1], 16;\n"
                 :: "r"(dst), "l"(src));
}
__device__ __forceinline__ void ldsm4(unsigned* r, unsigned addr) {
    asm volatile("ldmatrix.sync.aligned.m8n8.x4.shared.b16 {%0,%1,%2,%3}, [%4];"
                 : "=r"(r[0]), "=r"(r[1]), "=r"(r[2]), "=r"(r[3]) : "r"(addr));
}
__device__ __forceinline__ void mma16816(float* c, const unsigned* a,
                                         unsigned b0, unsigned b1) {
    asm volatile(
        "mma.sync.aligned.m16n8k16.row.col.f32.bf16.bf16.f32 "
        "{%0,%1,%2,%3}, {%4,%5,%6,%7}, {%8,%9}, {%0,%1,%2,%3};"
        : "+f"(c[0]), "+f"(c[1]), "+f"(c[2]), "+f"(c[3])
        : "r"(a[0]), "r"(a[1]), "r"(a[2]), "r"(a[3]), "r"(b0), "r"(b1));
}

// ---- smem layout (bytes) ----
#define SM_BIAS 0
#define SM_TILE 1024
#define T_A     0                // 128 pix * 128B = 16384
#define T_B     16384            // 128 oc * 128B = 16384
#define STG     32768
#define SMEM_TOTAL (SM_TILE + 3 * STG)   // 99328  -> 2 CTAs/SM

__global__ __launch_bounds__(NT, 2)
void conv_hmma_kernel(const float* __restrict__ bias, float* __restrict__ out) {
    extern __shared__ char smem[];
    const int tid  = threadIdx.x;
    const int lane = tid & 31;
    const int wid  = tid >> 5;
    const int m0   = blockIdx.x * BM;
    const int n0   = blockIdx.y * BN;

    ((float*)(smem + SM_BIAS))[tid] = bias[tid];   // NT == OC_

    // producer geometry: pix = tid&127, 16 channel-words per thread
    const int pix  = tid & 127;
    const int half = tid >> 7;            // 0..1
    const int p    = m0 + pix;
    const int bimg = p / HW_;
    const int hw   = p - bimg * HW_;
    const int h    = hw / W_;
    const int w    = hw - h * W_;
    // padded base for (c=0, kh=0, kw=0): index (h + kh, w + kw)
    const unsigned* xpb = g_xp + ((size_t)(bimg * C_) * HP + h) * WP + w;

    auto load_stage = [&](int s, int slot) {
        char* stg = smem + SM_TILE + slot * STG;
        // A tile: one tap, 32 consecutive channels, stride HWP
        int tap = s >> 2;                  // 0..8
        int c0  = (s & 3) << 5;            // 0,32,64,96
        int kh  = tap / 3;
        int kw  = tap - 3 * kh;
        const unsigned* src = xpb + (size_t)(c0 + half) * HWP + kh * WP + kw;
        const unsigned abase_s = smem_u32(stg + T_A);
#pragma unroll
        for (int j = 0; j < 16; j++) {
            int wk = half + 2 * j;
            // swizzle must see the FULL tile-relative offset (row bits feed XOR)
            cpa4(abase_s + sw128((unsigned)(pix * 128 + wk * 4)),
                 src + (size_t)(2 * j) * HWP);
        }
        // B tile: contiguous 16B chunks, 4 per thread (1024 total)
#pragma unroll
        for (int i = 0; i < 4; i++) {
            int q  = tid + NT * i;           // 0..1023
            int oc = q >> 3;                 // 0..127
            int ch = q & 7;
            const unsigned* bsrc = g_wi + (size_t)(n0 + oc) * KDIM + s * BKW + ch * 4;
            cpa16(smem_u32(stg + T_B + sw128((unsigned)(oc * 128 + ch * 16))), bsrc);
        }
        asm volatile("cp.async.commit_group;\n");
    };

    // warp tiling: 2 (M) x 4 (N) warps, warp tile 64 x 32
    const int wm = (wid & 1) * 64;
    const int wn = (wid >> 1) * 32;

    float acc[4][4][4];
#pragma unroll
    for (int a = 0; a < 4; a++)
#pragma unroll
        for (int b = 0; b < 4; b++)
#pragma unroll
            for (int cq = 0; cq < 4; cq++) acc[a][b][cq] = 0.0f;

    load_stage(0, 0);
    load_stage(1, 1);

    int slot = 0, slot2 = 2;    // slot of s, slot of s+2
    for (int s = 0; s < NSTAGE; s++) {
        asm volatile("cp.async.wait_group 1;\n");
        __syncthreads();

        if (s + 2 < NSTAGE) load_stage(s + 2, slot2);
        else asm volatile("cp.async.commit_group;\n");

        char* stg = smem + SM_TILE + slot * STG;
        const unsigned abase = smem_u32(stg + T_A);
        const unsigned bbase = smem_u32(stg + T_B);

#pragma unroll
        for (int pp = 0; pp < 2; pp++) {        // pair of 16-k' chunks
            unsigned afrE[4][4], afrO[4][4];
#pragma unroll
            for (int mi = 0; mi < 4; mi++) {
                int row = wm + mi * 16 + (lane & 15);
                unsigned base = (unsigned)(row * 128 + (lane >> 4) * 16);
                ldsm4(afrE[mi], abase + sw128(base + (2 * pp + 0) * 32));
                ldsm4(afrO[mi], abase + sw128(base + (2 * pp + 1) * 32));
            }
            // synthesize pure-hi A fragments (hi = bytes 2,3 of (lo|hi) word)
            unsigned ahi[4][4];
#pragma unroll
            for (int mi = 0; mi < 4; mi++) {
                ahi[mi][0] = __byte_perm(afrE[mi][0], afrE[mi][2], 0x7632);
                ahi[mi][1] = __byte_perm(afrE[mi][1], afrE[mi][3], 0x7632);
                ahi[mi][2] = __byte_perm(afrO[mi][0], afrO[mi][2], 0x7632);
                ahi[mi][3] = __byte_perm(afrO[mi][1], afrO[mi][3], 0x7632);
            }
#pragma unroll
            for (int ni = 0; ni < 2; ni++) {       // 16 oc per ldsm4
                unsigned bE[4], bO[4];
                int g   = lane >> 3;
                int r   = lane & 7;
                int ocl = wn + ni * 16 + ((g & 2) ? 8 : 0) + r;
                unsigned base = (unsigned)(ocl * 128 + (g & 1) * 16);
                ldsm4(bE, bbase + sw128(base + (2 * pp + 0) * 32));
                ldsm4(bO, bbase + sw128(base + (2 * pp + 1) * 32));
                // pass 2: interleaved corrections (a_lo*b_hi + a_hi*b_lo)
#pragma unroll
                for (int mi = 0; mi < 4; mi++) {
                    mma16816(acc[mi][ni * 2 + 0], afrE[mi], bE[0], bE[1]);
                    mma16816(acc[mi][ni * 2 + 1], afrE[mi], bE[2], bE[3]);
                    mma16816(acc[mi][ni * 2 + 0], afrO[mi], bO[0], bO[1]);
                    mma16816(acc[mi][ni * 2 + 1], afrO[mi], bO[2], bO[3]);
                }
                // pass 1: main hi*hi term (hi = bytes 0,1 of (hi|lo) word)
                unsigned bh0 = __byte_perm(bE[0], bE[1], 0x5410);
                unsigned bh1 = __byte_perm(bO[0], bO[1], 0x5410);
                unsigned bh2 = __byte_perm(bE[2], bE[3], 0x5410);
                unsigned bh3 = __byte_perm(bO[2], bO[3], 0x5410);
#pragma unroll
                for (int mi = 0; mi < 4; mi++) {
                    mma16816(acc[mi][ni * 2 + 0], ahi[mi], bh0, bh1);
                    mma16816(acc[mi][ni * 2 + 1], ahi[mi], bh2, bh3);
                }
            }
        }

        slot  = (slot  == 2) ? 0 : slot  + 1;
        slot2 = (slot2 == 2) ? 0 : slot2 + 1;
    }

    __syncthreads();

    // ---- epilogue: transpose through smem, coalesced float4 stores ----
    float* Cs = (float*)(smem + SM_TILE);   // [oc 128][pix 128] = 64KB
#pragma unroll
    for (int mi = 0; mi < 4; mi++)
#pragma unroll
        for (int nq = 0; nq < 4; nq++) {
            int r0 = wm + mi * 16 + (lane >> 2);
            int cb = wn + nq * 8 + (lane & 3) * 2;
            Cs[(cb + 0) * BM + r0]     = acc[mi][nq][0];
            Cs[(cb + 1) * BM + r0]     = acc[mi][nq][1];
            Cs[(cb + 0) * BM + r0 + 8] = acc[mi][nq][2];
            Cs[(cb + 1) * BM + r0 + 8] = acc[mi][nq][3];
        }
    __syncthreads();

    const float* bs = (const float*)(smem + SM_BIAS);
    for (int g = tid; g < BN * (BM / 4); g += NT) {     // 128 oc * 32 groups
        int ocl  = g >> 5;
        int pixl = (g & 31) * 4;
        int pp   = m0 + pixl;
        int bi   = pp / HW_;
        int off  = pp - bi * HW_;
        int oc   = n0 + ocl;
        float4 v = *(const float4*)&Cs[ocl * BM + pixl];
        float bv = bs[oc];
        v.x += bv; v.y += bv; v.z += bv; v.w += bv;
        *(float4*)(out + (size_t)bi * OC_ * HW_ + (size_t)oc * HW_ + off) = v;
    }
}

extern "C" void kernel_launch(void* const* d_in, const int* in_sizes, int n_in,
                              void* d_out, int out_size) {
    const float* x  = (const float*)d_in[0];
    const float* Wm = (const float*)d_in[1];
    const float* bb = (const float*)d_in[2];
    float* out      = (float*)d_out;

    int total = NX_ + NW_;
    prep_kernel<<<(total + 255) / 256, 256>>>(x, Wm);

    cudaFuncSetAttribute(conv_hmma_kernel,
                         cudaFuncAttributeMaxDynamicSharedMemorySize, SMEM_TOTAL);
    dim3 grid(M_ / BM, OC_ / BN);   // 784 x 2
    conv_hmma_kernel<<<grid, NT, SMEM_TOTAL>>>(bb, out);
}

// round 10
// speedup vs baseline: 2.2391x; 1.0024x over previous
#include <cuda_runtime.h>
#include <cuda_bf16.h>
#include <cstdint>

#define B_    32
#define C_    128
#define H_    56
#define W_    56
#define OC_   256
#define HW_   (H_ * W_)          // 3136
#define KDIM  1152               // C*9
#define M_    (B_ * HW_)         // 100352
#define NX_   (B_ * C_ * HW_)    // 12845056
#define NW_   (OC_ * KDIM)       // 294912

#define HP    58                 // padded H
#define WP    58                 // padded W
#define HWP   (HP * WP)          // 3364
#define NXP_  (B_ * C_ * HWP)    // 13787136

#define BM    128
#define BN    128
#define BKW   32                 // k' per stage (one tap, 32 channels)
#define NSTAGE 36                // 9 taps * 4 channel-chunks
#define NT    256                // 8 warps

// ---- static device scratch ----
__device__ unsigned g_xp[NXP_];                 // padded packed x, halo = 0 (bss)
__device__ __align__(16) unsigned g_wi[NW_];    // [oc][tap*128+c] = (b_hi | b_lo<<16)

__device__ __forceinline__ unsigned pack_x(float f) {
    __nv_bfloat16 hb = __float2bfloat16(f);
    float fh = __bfloat162float(hb);
    __nv_bfloat16 lb = __float2bfloat16(f - fh);
    return (unsigned)__bfloat16_as_ushort(lb)
         | ((unsigned)__bfloat16_as_ushort(hb) << 16);   // (lo | hi<<16)
}

__global__ void prep_kernel(const float* __restrict__ x,
                            const float* __restrict__ Wm) {
    int i = blockIdx.x * blockDim.x + threadIdx.x;
    if (i < NX_) {
        int bc = i / HW_;
        int r  = i - bc * HW_;
        int h  = r / W_;
        int w  = r - h * W_;
        g_xp[(bc * HP + h + 1) * WP + w + 1] = pack_x(x[i]);
    } else {
        int j = i - NX_;
        if (j < NW_) {
            int oc  = j / KDIM;
            int r   = j - oc * KDIM;
            int c   = r / 9;
            int tap = r - c * 9;
            float f = Wm[j];
            __nv_bfloat16 hb = __float2bfloat16(f);
            float fh = __bfloat162float(hb);
            __nv_bfloat16 lb = __float2bfloat16(f - fh);
            g_wi[oc * KDIM + tap * 128 + c] =
                  (unsigned)__bfloat16_as_ushort(hb)
                | ((unsigned)__bfloat16_as_ushort(lb) << 16);   // (hi | lo<<16)
        }
    }
}

// ---- helpers ----
__device__ __forceinline__ unsigned smem_u32(const void* p) {
    return (unsigned)__cvta_generic_to_shared(p);
}
__device__ __forceinline__ unsigned sw128(unsigned off) {
    return off ^ ((off >> 3) & 0x70);
}
__device__ __forceinline__ void cpa4(unsigned dst, const void* src) {
    asm volatile("cp.async.ca.shared.global [%0], [%1], 4;\n"
                 :: "r"(dst), "l"(src));
}
__device__ __forceinline__ void cpa16(unsigned dst, const void* src) {
    asm volatile("cp.async.cg.shared.global [%0], [%1], 16;\n"
                 :: "r"(dst), "l"(src));
}
__device__ __forceinline__ void ldsm4(unsigned* r, unsigned addr) {
    asm volatile("ldmatrix.sync.aligned.m8n8.x4.shared.b16 {%0,%1,%2,%3}, [%4];"
                 : "=r"(r[0]), "=r"(r[1]), "=r"(r[2]), "=r"(r[3]) : "r"(addr));
}
// NOTE: non-volatile — register-only op, lets the compiler schedule freely
__device__ __forceinline__ void mma16816(float* c, const unsigned* a,
                                         unsigned b0, unsigned b1) {
    asm("mma.sync.aligned.m16n8k16.row.col.f32.bf16.bf16.f32 "
        "{%0,%1,%2,%3}, {%4,%5,%6,%7}, {%8,%9}, {%0,%1,%2,%3};"
        : "+f"(c[0]), "+f"(c[1]), "+f"(c[2]), "+f"(c[3])
        : "r"(a[0]), "r"(a[1]), "r"(a[2]), "r"(a[3]), "r"(b0), "r"(b1));
}

// ---- smem layout (bytes) ----
#define SM_BIAS 0
#define SM_TILE 1024
#define T_A     0                // 128 pix * 128B = 16384
#define T_B     16384            // 128 oc * 128B = 16384
#define STG     32768
#define SMEM_TOTAL (SM_TILE + 3 * STG)   // 99328  -> 2 CTAs/SM

__global__ __launch_bounds__(NT, 2)
void conv_hmma_kernel(const float* __restrict__ bias, float* __restrict__ out) {
    extern __shared__ char smem[];
    const int tid  = threadIdx.x;
    const int lane = tid & 31;
    const int wid  = tid >> 5;
    const int m0   = blockIdx.x * BM;
    const int n0   = blockIdx.y * BN;

    ((float*)(smem + SM_BIAS))[tid] = bias[tid];   // NT == OC_

    // producer geometry: pix = tid&127, 16 channel-words per thread
    const int pix  = tid & 127;
    const int half = tid >> 7;            // 0..1
    const int p    = m0 + pix;
    const int bimg = p / HW_;
    const int hw   = p - bimg * HW_;
    const int h    = hw / W_;
    const int w    = hw - h * W_;
    const unsigned* xpb = g_xp + ((size_t)(bimg * C_) * HP + h) * WP + w;

    auto load_stage = [&](int s, int slot) {
        char* stg = smem + SM_TILE + slot * STG;
        int tap = s >> 2;                  // 0..8
        int c0  = (s & 3) << 5;            // 0,32,64,96
        int kh  = tap / 3;
        int kw  = tap - 3 * kh;
        const unsigned* src = xpb + (size_t)(c0 + half) * HWP + kh * WP + kw;
        const unsigned abase_s = smem_u32(stg + T_A);
#pragma unroll
        for (int j = 0; j < 16; j++) {
            int wk = half + 2 * j;
            cpa4(abase_s + sw128((unsigned)(pix * 128 + wk * 4)),
                 src + (size_t)(2 * j) * HWP);
        }
#pragma unroll
        for (int i = 0; i < 4; i++) {
            int q  = tid + NT * i;           // 0..1023
            int oc = q >> 3;                 // 0..127
            int ch = q & 7;
            const unsigned* bsrc = g_wi + (size_t)(n0 + oc) * KDIM + s * BKW + ch * 4;
            cpa16(smem_u32(stg + T_B + sw128((unsigned)(oc * 128 + ch * 16))), bsrc);
        }
        asm volatile("cp.async.commit_group;\n");
    };

    // warp tiling: 2 (M) x 4 (N) warps, warp tile 64 x 32
    const int wm = (wid & 1) * 64;
    const int wn = (wid >> 1) * 32;

    float acc[4][4][4];
#pragma unroll
    for (int a = 0; a < 4; a++)
#pragma unroll
        for (int b = 0; b < 4; b++)
#pragma unroll
            for (int cq = 0; cq < 4; cq++) acc[a][b][cq] = 0.0f;

    load_stage(0, 0);
    load_stage(1, 1);

    int slot = 0, slot2 = 2;
    for (int s = 0; s < NSTAGE; s++) {
        asm volatile("cp.async.wait_group 1;\n");
        __syncthreads();

        if (s + 2 < NSTAGE) load_stage(s + 2, slot2);
        else asm volatile("cp.async.commit_group;\n");

        char* stg = smem + SM_TILE + slot * STG;
        const unsigned abase = smem_u32(stg + T_A);
        const unsigned bbase = smem_u32(stg + T_B);

#pragma unroll
        for (int pp = 0; pp < 2; pp++) {
            unsigned afrE[4][4], afrO[4][4];
#pragma unroll
            for (int mi = 0; mi < 4; mi++) {
                int row = wm + mi * 16 + (lane & 15);
                unsigned base = (unsigned)(row * 128 + (lane >> 4) * 16);
                ldsm4(afrE[mi], abase + sw128(base + (2 * pp + 0) * 32));
                ldsm4(afrO[mi], abase + sw128(base + (2 * pp + 1) * 32));
            }
            unsigned ahi[4][4];
#pragma unroll
            for (int mi = 0; mi < 4; mi++) {
                ahi[mi][0] = __byte_perm(afrE[mi][0], afrE[mi][2], 0x7632);
                ahi[mi][1] = __byte_perm(afrE[mi][1], afrE[mi][3], 0x7632);
                ahi[mi][2] = __byte_perm(afrO[mi][0], afrO[mi][2], 0x7632);
                ahi[mi][3] = __byte_perm(afrO[mi][1], afrO[mi][3], 0x7632);
            }
#pragma unroll
            for (int ni = 0; ni < 2; ni++) {
                unsigned bE[4], bO[4];
                int g   = lane >> 3;
                int r   = lane & 7;
                int ocl = wn + ni * 16 + ((g & 2) ? 8 : 0) + r;
                unsigned base = (unsigned)(ocl * 128 + (g & 1) * 16);
                ldsm4(bE, bbase + sw128(base + (2 * pp + 0) * 32));
                ldsm4(bO, bbase + sw128(base + (2 * pp + 1) * 32));
                // hi-B extraction up front so PRMT latency hides under E/O MMAs
                unsigned bh0 = __byte_perm(bE[0], bE[1], 0x5410);
                unsigned bh1 = __byte_perm(bO[0], bO[1], 0x5410);
                unsigned bh2 = __byte_perm(bE[2], bE[3], 0x5410);
                unsigned bh3 = __byte_perm(bO[2], bO[3], 0x5410);
                // group 1: all-E (8 MMAs) — acc reuse distance vs O/hi = 8
#pragma unroll
                for (int mi = 0; mi < 4; mi++)
                    mma16816(acc[mi][ni * 2 + 0], afrE[mi], bE[0], bE[1]);
#pragma unroll
                for (int mi = 0; mi < 4; mi++)
                    mma16816(acc[mi][ni * 2 + 1], afrE[mi], bE[2], bE[3]);
                // group 2: all-O (8 MMAs)
#pragma unroll
                for (int mi = 0; mi < 4; mi++)
                    mma16816(acc[mi][ni * 2 + 0], afrO[mi], bO[0], bO[1]);
#pragma unroll
                for (int mi = 0; mi < 4; mi++)
                    mma16816(acc[mi][ni * 2 + 1], afrO[mi], bO[2], bO[3]);
                // group 3: all-hi (8 MMAs)
#pragma unroll
                for (int mi = 0; mi < 4; mi++)
                    mma16816(acc[mi][ni * 2 + 0], ahi[mi], bh0, bh1);
#pragma unroll
                for (int mi = 0; mi < 4; mi++)
                    mma16816(acc[mi][ni * 2 + 1], ahi[mi], bh2, bh3);
            }
        }

        slot  = (slot  == 2) ? 0 : slot  + 1;
        slot2 = (slot2 == 2) ? 0 : slot2 + 1;
    }

    __syncthreads();

    // ---- epilogue: transpose through smem, coalesced float4 stores ----
    float* Cs = (float*)(smem + SM_TILE);   // [oc 128][pix 128] = 64KB
#pragma unroll
    for (int mi = 0; mi < 4; mi++)
#pragma unroll
        for (int nq = 0; nq < 4; nq++) {
            int r0 = wm + mi * 16 + (lane >> 2);
            int cb = wn + nq * 8 + (lane & 3) * 2;
            Cs[(cb + 0) * BM + r0]     = acc[mi][nq][0];
            Cs[(cb + 1) * BM + r0]     = acc[mi][nq][1];
            Cs[(cb + 0) * BM + r0 + 8] = acc[mi][nq][2];
            Cs[(cb + 1) * BM + r0 + 8] = acc[mi][nq][3];
        }
    __syncthreads();

    const float* bs = (const float*)(smem + SM_BIAS);
    for (int g = tid; g < BN * (BM / 4); g += NT) {
        int ocl  = g >> 5;
        int pixl = (g & 31) * 4;
        int pp   = m0 + pixl;
        int bi   = pp / HW_;
        int off  = pp - bi * HW_;
        int oc   = n0 + ocl;
        float4 v = *(const float4*)&Cs[ocl * BM + pixl];
        float bv = bs[oc];
        v.x += bv; v.y += bv; v.z += bv; v.w += bv;
        *(float4*)(out + (size_t)bi * OC_ * HW_ + (size_t)oc * HW_ + off) = v;
    }
}

extern "C" void kernel_launch(void* const* d_in, const int* in_sizes, int n_in,
                              void* d_out, int out_size) {
    const float* x  = (const float*)d_in[0];
    const float* Wm = (const float*)d_in[1];
    const float* bb = (const float*)d_in[2];
    float* out      = (float*)d_out;

    int total = NX_ + NW_;
    prep_kernel<<<(total + 255) / 256, 256>>>(x, Wm);

    cudaFuncSetAttribute(conv_hmma_kernel,
                         cudaFuncAttributeMaxDynamicSharedMemorySize, SMEM_TOTAL);
    dim3 grid(M_ / BM, OC_ / BN);   // 784 x 2
    conv_hmma_kernel<<<grid, NT, SMEM_TOTAL>>>(bb, out);
}